// round 6
// baseline (speedup 1.0000x reference)
#include <cuda_runtime.h>
#include <cstdint>

// ---------------------------------------------------------------------------
// Problem constants
//   B=8, Cf=512, Cg=256, HID=256, Co=256, H=W=64, HW=4096, pool 16x16 -> 16 KV
// ---------------------------------------------------------------------------
#define HW    4096
#define NB    8
#define HIDN  256

// ---------------------------------------------------------------------------
// Device scratch (no allocation allowed -> __device__ globals)
// ---------------------------------------------------------------------------
__device__ float g_wqf[512 * 256];          // gamma-folded wq
__device__ float g_wkf[256 * 256];
__device__ float g_wvf[256 * 256];
__device__ float g_Sq[256], g_Tq[256];
__device__ float g_Sk[256], g_Tk[256];
__device__ float g_Svv[256], g_Tvv[256];
__device__ float g_fs[256], g_fb[256];      // folded BN scale/shift (incl outc_b)
__device__ float g_rf[NB * HW], g_af[NB * HW];   // e_f LN: rstd, -rstd*mean
__device__ float g_rg[NB * HW], g_ag[NB * HW];   // e_g LN
__device__ float g_q   [NB * 256 * HW];
__device__ float g_k   [NB * 256 * HW];
__device__ float g_v   [NB * 256 * HW];
__device__ float g_a   [NB * 256 * HW];     // attention output
__device__ float g_cin [NB * 256 * HW];     // dwconv + attn
__device__ float g_comb[NB * 256 * HW];     // wo projection
__device__ float g_efp [NB * 256 * HW];     // 1x1 proj of e_f
__device__ float g_kp[NB * 16 * 256];       // pooled K
__device__ float g_vp[NB * 16 * 256];       // pooled V

// ---------------------------------------------------------------------------
// Prep: fold LN gammas into weights, compute S/T vectors, fold BN
// ---------------------------------------------------------------------------
__global__ void prep_kernel(const float* __restrict__ wq, const float* __restrict__ bq,
                            const float* __restrict__ gf, const float* __restrict__ bf,
                            const float* __restrict__ wk, const float* __restrict__ bk,
                            const float* __restrict__ gg, const float* __restrict__ bg,
                            const float* __restrict__ wv, const float* __restrict__ bv,
                            const float* __restrict__ outc_b,
                            const float* __restrict__ bn_g, const float* __restrict__ bn_b,
                            const float* __restrict__ bn_m, const float* __restrict__ bn_v)
{
    int j = threadIdx.x;  // 0..255
    if (blockIdx.x == 0) {
        float S = 0.f, T = 0.f;
        for (int c = 0; c < 512; c++) {
            float w = wq[c * 256 + j];
            float f = w * gf[c];
            g_wqf[c * 256 + j] = f;
            S += f; T += w * bf[c];
        }
        g_Sq[j] = S; g_Tq[j] = T + bq[j];
    } else if (blockIdx.x == 1) {
        float S = 0.f, T = 0.f;
        for (int c = 0; c < 256; c++) {
            float w = wk[c * 256 + j];
            float f = w * gg[c];
            g_wkf[c * 256 + j] = f;
            S += f; T += w * bg[c];
        }
        g_Sk[j] = S; g_Tk[j] = T + bk[j];
    } else if (blockIdx.x == 2) {
        float S = 0.f, T = 0.f;
        for (int c = 0; c < 256; c++) {
            float w = wv[c * 256 + j];
            float f = w * gg[c];
            g_wvf[c * 256 + j] = f;
            S += f; T += w * bg[c];
        }
        g_Svv[j] = S; g_Tvv[j] = T + bv[j];
    } else {
        float sc = bn_g[j] * rsqrtf(bn_v[j] + 1e-5f);
        g_fs[j] = sc;
        g_fb[j] = (outc_b[j] - bn_m[j]) * sc + bn_b[j];
    }
}

// ---------------------------------------------------------------------------
// Per-pixel LN statistics over the channel dim. NCHW: threads = adjacent
// pixels -> every channel pass is a fully coalesced load.
// ---------------------------------------------------------------------------
template <int WHICH>
__global__ void stats_kernel(const float* __restrict__ X)
{
    constexpr int C = (WHICH == 0) ? 512 : 256;
    int gid = blockIdx.x * 256 + threadIdx.x;        // 0..32767
    const float* base = X + (size_t)(gid >> 12) * C * HW + (gid & (HW - 1));
    float s = 0.f, s2 = 0.f;
#pragma unroll 8
    for (int c = 0; c < C; c++) {
        float v = base[(size_t)c * HW];
        s += v; s2 = fmaf(v, v, s2);
    }
    const float invC = 1.0f / (float)C;
    float m = s * invC;
    float var = fmaf(-m, m, s2 * invC);
    float r = rsqrtf(var + 1e-5f);
    if (WHICH == 0) { g_rf[gid] = r; g_af[gid] = -r * m; }
    else            { g_rg[gid] = r; g_ag[gid] = -r * m; }
}

// ---------------------------------------------------------------------------
// Generic tiled fp32 GEMM: C[j][p] = sum_c W[c][j] * X[c][p], 64x64x16 tile,
// 256 threads, 4x4 microtile, fused per-CFG prologue/epilogue:
//   CFG 0/1/2 : LN-folded epilogue  r_p*acc + a_p*S_j + T_j   (q/k/v)
//   CFG 3     : plain + bias                                   (wo)
//   CFG 4     : plain + bias, W transposed [j][c]              (efp)
//   CFG 5     : gated (X * g_comb) + BN + ReLU, W transposed   (final out)
// ---------------------------------------------------------------------------
template <int CFG>
__global__ __launch_bounds__(256)
void gemm_kernel(const float* __restrict__ Wext,
                 const float* __restrict__ Xext,
                 const float* __restrict__ Bext,
                 float* __restrict__ Cext,
                 int K)
{
    constexpr int  MODE = (CFG <= 2) ? 0 : ((CFG <= 4) ? 1 : 2);
    constexpr bool WT   = (CFG >= 4);

    const float* W = (CFG == 0) ? g_wqf : (CFG == 1) ? g_wkf : (CFG == 2) ? g_wvf : Wext;
    const float* X = (CFG == 3) ? g_cin : (CFG == 5) ? g_efp : Xext;
    float*       C = (CFG == 0) ? g_q   : (CFG == 1) ? g_k   : (CFG == 2) ? g_v
                   : (CFG == 3) ? g_comb: (CFG == 4) ? g_efp : Cext;

    const int b  = blockIdx.z;
    const int pb = blockIdx.x * 64;
    const int jb = blockIdx.y * 64;
    const float* Xb = X + (size_t)b * K * HW;

    __shared__ __align__(16) float As[16][64];
    __shared__ __align__(16) float Xs[16][64];

    const int tid = threadIdx.x;
    const int tx  = tid & 15;
    const int ty  = tid >> 4;
    float acc[4][4] = {};

    for (int kt = 0; kt < K; kt += 16) {
        if (!WT) {
            int kk = tid >> 4, j4 = (tid & 15) << 2;
            float4 wv = *(const float4*)(W + (size_t)(kt + kk) * 256 + jb + j4);
            *(float4*)&As[kk][j4] = wv;
        } else {
            int j = tid >> 2, kq = (tid & 3) << 2;
            float4 wv = *(const float4*)(W + (size_t)(jb + j) * K + kt + kq);
            As[kq + 0][j] = wv.x; As[kq + 1][j] = wv.y;
            As[kq + 2][j] = wv.z; As[kq + 3][j] = wv.w;
        }
        {
            int kk = tid >> 4, p4 = (tid & 15) << 2;
            size_t off = (size_t)(kt + kk) * HW + pb + p4;
            float4 xv = *(const float4*)(Xb + off);
            if (MODE == 2) {
                const float* X2b = g_comb + (size_t)b * 256 * HW;
                float4 yv = *(const float4*)(X2b + off);
                xv.x *= yv.x; xv.y *= yv.y; xv.z *= yv.z; xv.w *= yv.w;
            }
            *(float4*)&Xs[kk][p4] = xv;
        }
        __syncthreads();
#pragma unroll
        for (int kk = 0; kk < 16; kk++) {
            float av[4], bv[4];
#pragma unroll
            for (int i = 0; i < 4; i++) av[i] = As[kk][ty + 16 * i];
#pragma unroll
            for (int l = 0; l < 4; l++) bv[l] = Xs[kk][tx + 16 * l];
#pragma unroll
            for (int i = 0; i < 4; i++)
#pragma unroll
                for (int l = 0; l < 4; l++)
                    acc[i][l] = fmaf(av[i], bv[l], acc[i][l]);
        }
        __syncthreads();
    }

    float* Cb = C + (size_t)b * 256 * HW;
    if (MODE == 0) {
        const float* rv  = (CFG == 0) ? g_rf : g_rg;
        const float* avv = (CFG == 0) ? g_af : g_ag;
        const float* Sv  = (CFG == 0) ? g_Sq : (CFG == 1) ? g_Sk : g_Svv;
        const float* Tv  = (CFG == 0) ? g_Tq : (CFG == 1) ? g_Tk : g_Tvv;
        float rr[4], aa[4];
#pragma unroll
        for (int l = 0; l < 4; l++) {
            int p = pb + tx + 16 * l;
            rr[l] = rv [b * HW + p];
            aa[l] = avv[b * HW + p];
        }
#pragma unroll
        for (int i = 0; i < 4; i++) {
            int j = jb + ty + 16 * i;
            float S = Sv[j], T = Tv[j];
#pragma unroll
            for (int l = 0; l < 4; l++) {
                int p = pb + tx + 16 * l;
                Cb[(size_t)j * HW + p] = fmaf(rr[l], acc[i][l], fmaf(aa[l], S, T));
            }
        }
    } else if (MODE == 1) {
#pragma unroll
        for (int i = 0; i < 4; i++) {
            int j = jb + ty + 16 * i;
            float bb = Bext[j];
#pragma unroll
            for (int l = 0; l < 4; l++) {
                int p = pb + tx + 16 * l;
                Cb[(size_t)j * HW + p] = acc[i][l] + bb;
            }
        }
    } else {
#pragma unroll
        for (int i = 0; i < 4; i++) {
            int j = jb + ty + 16 * i;
            float fs = g_fs[j], fb = g_fb[j];
#pragma unroll
            for (int l = 0; l < 4; l++) {
                int p = pb + tx + 16 * l;
                float v = fmaf(acc[i][l], fs, fb);
                Cb[(size_t)j * HW + p] = fmaxf(v, 0.0f);
            }
        }
    }
}

// ---------------------------------------------------------------------------
// 16x16 max-pool (K) + avg-pool (V). Block = (batch, cell-row); thread covers
// (channel, cell-col); float4 rows keep the 512B warp transaction dense.
// ---------------------------------------------------------------------------
__global__ void pool_kernel()
{
    int bc = blockIdx.x;         // 0..31  (b*4 + cell_row)
    int b  = bc >> 2;
    int ch = bc & 3;
    int d0 = threadIdx.x >> 2;   // 0..63
    int cw = threadIdx.x & 3;    // 0..3

    for (int dc = 0; dc < 4; dc++) {
        int d = dc * 64 + d0;
        size_t base = (size_t)(b * 256 + d) * HW + (size_t)(ch * 16) * 64 + cw * 16;
        float mx = -3.4e38f, sm = 0.f;
        for (int hh = 0; hh < 16; hh++) {
            const float4* kr = (const float4*)(g_k + base + hh * 64);
            const float4* vr = (const float4*)(g_v + base + hh * 64);
#pragma unroll
            for (int i = 0; i < 4; i++) {
                float4 kv = kr[i], vv = vr[i];
                mx = fmaxf(mx, fmaxf(fmaxf(kv.x, kv.y), fmaxf(kv.z, kv.w)));
                sm += (vv.x + vv.y) + (vv.z + vv.w);
            }
        }
        int cell = ch * 4 + cw;
        g_kp[(b * 16 + cell) * 256 + d] = mx;
        g_vp[(b * 16 + cell) * 256 + d] = sm * (1.0f / 256.0f);
    }
}

// ---------------------------------------------------------------------------
// Pooled attention: 16 KV tokens in SMEM, thread = one query pixel.
// ---------------------------------------------------------------------------
__global__ __launch_bounds__(256)
void attn_kernel()
{
    __shared__ float ks[4096];
    __shared__ float vs[4096];
    int b   = blockIdx.y;
    int pix = blockIdx.x * 256 + threadIdx.x;

    for (int i = threadIdx.x; i < 4096; i += 256) {
        ks[i] = g_kp[b * 4096 + i];
        vs[i] = g_vp[b * 4096 + i];
    }
    __syncthreads();

    float s[16];
#pragma unroll
    for (int t = 0; t < 16; t++) s[t] = 0.f;

    const float* qb = g_q + (size_t)b * 256 * HW + pix;
    for (int d = 0; d < 256; d++) {
        float qd = qb[(size_t)d * HW];
#pragma unroll
        for (int t = 0; t < 16; t++)
            s[t] = fmaf(qd, ks[t * 256 + d], s[t]);
    }
    float m = -3.4e38f;
#pragma unroll
    for (int t = 0; t < 16; t++) { s[t] *= 0.0625f; m = fmaxf(m, s[t]); }
    float sum = 0.f;
#pragma unroll
    for (int t = 0; t < 16; t++) { s[t] = __expf(s[t] - m); sum += s[t]; }
    float inv = 1.0f / sum;
#pragma unroll
    for (int t = 0; t < 16; t++) s[t] *= inv;

    float* ab = g_a + (size_t)b * 256 * HW + pix;
    for (int d = 0; d < 256; d++) {
        float acc = 0.f;
#pragma unroll
        for (int t = 0; t < 16; t++)
            acc = fmaf(s[t], vs[t * 256 + d], acc);
        ab[(size_t)d * HW] = acc;
    }
}

// ---------------------------------------------------------------------------
// Depthwise 3x3 on Q (cross-correlation, zero pad) + attention add.
// Each thread handles 4 consecutive pixels in one row -> kernel-row loads are
// reused across the 4 outputs and launch count drops 4x.
// ---------------------------------------------------------------------------
__global__ __launch_bounds__(256)
void dwadd_kernel(const float* __restrict__ dwk)
{
    int bc   = blockIdx.y;             // b*256 + c
    int c    = bc & 255;
    int pix0 = (blockIdx.x * 256 + threadIdx.x) * 4;   // 4 pixels per thread
    int h = pix0 >> 6, w0 = pix0 & 63;

    float k0 = dwk[c * 9 + 0], k1 = dwk[c * 9 + 1], k2 = dwk[c * 9 + 2];
    float k3 = dwk[c * 9 + 3], k4 = dwk[c * 9 + 4], k5 = dwk[c * 9 + 5];
    float k6 = dwk[c * 9 + 6], k7 = dwk[c * 9 + 7], k8 = dwk[c * 9 + 8];

    const float* qc = g_q + (size_t)bc * HW;
    const float* ac = g_a + (size_t)bc * HW;
    float*       oc = g_cin + (size_t)bc * HW;

    float acc[4];
#pragma unroll
    for (int i = 0; i < 4; i++) acc[i] = ac[pix0 + i];

#pragma unroll
    for (int dy = -1; dy <= 1; dy++) {
        int hh = h + dy;
        if (hh < 0 || hh > 63) continue;
        const float* row = qc + hh * 64;
        float ka = (dy == -1) ? k0 : (dy == 0) ? k3 : k6;
        float kb = (dy == -1) ? k1 : (dy == 0) ? k4 : k7;
        float kc = (dy == -1) ? k2 : (dy == 0) ? k5 : k8;
        // load the 6 pixels covering w0-1 .. w0+4
        float x[6];
#pragma unroll
        for (int i = 0; i < 6; i++) {
            int ww = w0 - 1 + i;
            x[i] = (ww >= 0 && ww <= 63) ? row[ww] : 0.0f;
        }
#pragma unroll
        for (int i = 0; i < 4; i++) {
            acc[i] = fmaf(ka, x[i], acc[i]);
            acc[i] = fmaf(kb, x[i + 1], acc[i]);
            acc[i] = fmaf(kc, x[i + 2], acc[i]);
        }
    }
#pragma unroll
    for (int i = 0; i < 4; i++) oc[pix0 + i] = acc[i];
}

// ---------------------------------------------------------------------------
// Launch
// ---------------------------------------------------------------------------
extern "C" void kernel_launch(void* const* d_in, const int* in_sizes, int n_in,
                              void* d_out, int out_size)
{
    const float* e_f    = (const float*)d_in[0];
    const float* e_g    = (const float*)d_in[1];
    // d_in[2] l_feat, d_in[3] l_mask: unused by the reference
    const float* ln_f_g = (const float*)d_in[4];
    const float* ln_f_b = (const float*)d_in[5];
    const float* ln_g_g = (const float*)d_in[6];
    const float* ln_g_b = (const float*)d_in[7];
    const float* wq     = (const float*)d_in[8];
    const float* bq     = (const float*)d_in[9];
    const float* wk     = (const float*)d_in[10];
    const float* bk     = (const float*)d_in[11];
    const float* wv     = (const float*)d_in[12];
    const float* bv     = (const float*)d_in[13];
    const float* wo     = (const float*)d_in[14];
    const float* bo     = (const float*)d_in[15];
    const float* dwk    = (const float*)d_in[16];
    const float* efp_w  = (const float*)d_in[17];
    const float* efp_b  = (const float*)d_in[18];
    const float* outc_w = (const float*)d_in[19];
    const float* outc_b = (const float*)d_in[20];
    const float* bn_g   = (const float*)d_in[21];
    const float* bn_b   = (const float*)d_in[22];
    const float* bn_m   = (const float*)d_in[23];
    const float* bn_v   = (const float*)d_in[24];
    float* out = (float*)d_out;

    prep_kernel<<<4, 256>>>(wq, bq, ln_f_g, ln_f_b,
                            wk, bk, ln_g_g, ln_g_b,
                            wv, bv, outc_b, bn_g, bn_b, bn_m, bn_v);
    stats_kernel<0><<<128, 256>>>(e_f);
    stats_kernel<1><<<128, 256>>>(e_g);

    dim3 gg(64, 4, 8);
    gemm_kernel<0><<<gg, 256>>>(nullptr, e_f, nullptr, nullptr, 512);   // Q
    gemm_kernel<1><<<gg, 256>>>(nullptr, e_g, nullptr, nullptr, 256);   // K
    gemm_kernel<2><<<gg, 256>>>(nullptr, e_g, nullptr, nullptr, 256);   // V

    pool_kernel<<<32, 256>>>();
    attn_kernel<<<dim3(16, 8), 256>>>();
    dwadd_kernel<<<dim3(4, 2048), 256>>>(dwk);

    gemm_kernel<3><<<gg, 256>>>(wo,     nullptr, bo,    nullptr, 256);  // comb = wo(combined)
    gemm_kernel<4><<<gg, 256>>>(efp_w,  e_f,     efp_b, nullptr, 512);  // efp
    gemm_kernel<5><<<gg, 256>>>(outc_w, nullptr, nullptr, out,   256);  // gated + BN + ReLU
}

// round 15
// speedup vs baseline: 1.0897x; 1.0897x over previous
#include <cuda_runtime.h>
#include <cuda_fp16.h>
#include <cstdint>

#define HW 4096
#define NB 8

// ---------------- device scratch (channel-major [b][c][p]) ----------------
__device__ uint32_t g_wh[262144];   // packed fp16 hi weights, [j][c/2], K-major
__device__ uint32_t g_wl[262144];   // packed fp16 lo (residual)
#define OWQ 0
#define OWK 65536
#define OWV 98304
#define OWO 131072
#define OWE 163840
#define OWC 229376
__device__ float g_Sq[256], g_Tq[256];
__device__ float g_Sk[256], g_Tk[256];
__device__ float g_Sv[256], g_Tv[256];
__device__ float g_fs[256], g_fb[256];
__device__ float g_rf[NB * HW], g_af[NB * HW];
__device__ float g_rg[NB * HW], g_ag[NB * HW];
__device__ float g_q   [NB * 256 * HW];
__device__ float g_k   [NB * 256 * HW];
__device__ float g_v   [NB * 256 * HW];
__device__ float g_a   [NB * 256 * HW];
__device__ float g_cin [NB * 256 * HW];
__device__ float g_comb[NB * 256 * HW];
__device__ float g_efp [NB * 256 * HW];
__device__ float g_kp[NB * 16 * 256];
__device__ float g_vp[NB * 16 * 256];

// ---------------- helpers ----------------
__device__ __forceinline__ uint32_t pack_hi(float x0, float x1, float& r0, float& r1) {
    __half h0 = __float2half_rn(x0), h1 = __float2half_rn(x1);
    r0 = x0 - __half2float(h0);
    r1 = x1 - __half2float(h1);
    return (uint32_t)__half_as_ushort(h0) | ((uint32_t)__half_as_ushort(h1) << 16);
}
__device__ __forceinline__ uint32_t pack2(float x0, float x1) {
    __half h0 = __float2half_rn(x0), h1 = __float2half_rn(x1);
    return (uint32_t)__half_as_ushort(h0) | ((uint32_t)__half_as_ushort(h1) << 16);
}
__device__ __forceinline__ void mma16(float* c, const uint32_t* a, const uint32_t* b) {
    asm volatile(
        "mma.sync.aligned.m16n8k16.row.col.f32.f16.f16.f32 "
        "{%0,%1,%2,%3}, {%4,%5,%6,%7}, {%8,%9}, {%0,%1,%2,%3};"
        : "+f"(c[0]), "+f"(c[1]), "+f"(c[2]), "+f"(c[3])
        : "r"(a[0]), "r"(a[1]), "r"(a[2]), "r"(a[3]), "r"(b[0]), "r"(b[1]));
}

// ---------------- prep: split+pack all weights (hi/lo fp16) ----------------
__global__ void fold_kernel(const float* __restrict__ wq, const float* __restrict__ gf,
                            const float* __restrict__ wk, const float* __restrict__ wv,
                            const float* __restrict__ gg, const float* __restrict__ wo,
                            const float* __restrict__ efp_w, const float* __restrict__ outc_w)
{
    int idx = blockIdx.x * 256 + threadIdx.x;   // 0..262143
    float x0, x1;
    if (idx < 65536) {                                    // wq folded, transpose -> [j][c]
        int j = idx >> 8, c = (idx & 255) * 2;
        x0 = wq[c * 256 + j] * gf[c];
        x1 = wq[(c + 1) * 256 + j] * gf[c + 1];
    } else if (idx < 98304) {                             // wk folded
        int r = idx - 65536, j = r >> 7, c = (r & 127) * 2;
        x0 = wk[c * 256 + j] * gg[c];
        x1 = wk[(c + 1) * 256 + j] * gg[c + 1];
    } else if (idx < 131072) {                            // wv folded
        int r = idx - 98304, j = r >> 7, c = (r & 127) * 2;
        x0 = wv[c * 256 + j] * gg[c];
        x1 = wv[(c + 1) * 256 + j] * gg[c + 1];
    } else if (idx < 163840) {                            // wo transpose
        int r = idx - 131072, j = r >> 7, c = (r & 127) * 2;
        x0 = wo[c * 256 + j];
        x1 = wo[(c + 1) * 256 + j];
    } else if (idx < 229376) {                            // efp_w direct [j][c]
        int r = idx - 163840, j = r >> 8, c = (r & 255) * 2;
        x0 = efp_w[j * 512 + c];
        x1 = efp_w[j * 512 + c + 1];
    } else {                                              // outc_w direct
        int r = idx - 229376, j = r >> 7, c = (r & 127) * 2;
        x0 = outc_w[j * 256 + c];
        x1 = outc_w[j * 256 + c + 1];
    }
    float r0, r1;
    g_wh[idx] = pack_hi(x0, x1, r0, r1);
    g_wl[idx] = pack2(r0, r1);
}

__global__ void vec_kernel(const float* __restrict__ wq, const float* __restrict__ bq,
                           const float* __restrict__ gf, const float* __restrict__ bf,
                           const float* __restrict__ wk, const float* __restrict__ bk,
                           const float* __restrict__ wv, const float* __restrict__ bv,
                           const float* __restrict__ gg, const float* __restrict__ bg,
                           const float* __restrict__ outc_b,
                           const float* __restrict__ bn_g, const float* __restrict__ bn_b,
                           const float* __restrict__ bn_m, const float* __restrict__ bn_v)
{
    int j = threadIdx.x;
    if (blockIdx.x == 0) {
        float S = 0.f, T = 0.f;
        for (int c = 0; c < 512; c++) {
            float w = wq[c * 256 + j];
            S = fmaf(w, gf[c], S); T = fmaf(w, bf[c], T);
        }
        g_Sq[j] = S; g_Tq[j] = T + bq[j];
    } else if (blockIdx.x == 1) {
        float S = 0.f, T = 0.f;
        for (int c = 0; c < 256; c++) {
            float w = wk[c * 256 + j];
            S = fmaf(w, gg[c], S); T = fmaf(w, bg[c], T);
        }
        g_Sk[j] = S; g_Tk[j] = T + bk[j];
    } else if (blockIdx.x == 2) {
        float S = 0.f, T = 0.f;
        for (int c = 0; c < 256; c++) {
            float w = wv[c * 256 + j];
            S = fmaf(w, gg[c], S); T = fmaf(w, bg[c], T);
        }
        g_Sv[j] = S; g_Tv[j] = T + bv[j];
    } else {
        float sc = bn_g[j] * rsqrtf(bn_v[j] + 1e-5f);
        g_fs[j] = sc;
        g_fb[j] = (outc_b[j] - bn_m[j]) * sc + bn_b[j];
    }
}

// ---------------- per-pixel LN stats (proven R5 version) ----------------
template <int WHICH>
__global__ void stats_kernel(const float* __restrict__ X)
{
    constexpr int C = (WHICH == 0) ? 512 : 256;
    int gid = blockIdx.x * 256 + threadIdx.x;
    const float* base = X + (size_t)(gid >> 12) * C * HW + (gid & (HW - 1));
    float s = 0.f, s2 = 0.f;
#pragma unroll 8
    for (int c = 0; c < C; c++) {
        float v = base[(size_t)c * HW];
        s += v; s2 = fmaf(v, v, s2);
    }
    const float invC = 1.0f / (float)C;
    float m = s * invC;
    float var = fmaf(-m, m, s2 * invC);
    float r = rsqrtf(var + 1e-5f);
    if (WHICH == 0) { g_rf[gid] = r; g_af[gid] = -r * m; }
    else            { g_rg[gid] = r; g_ag[gid] = -r * m; }
}

// ---------------- mma.sync fp16 3-term GEMM (channel-major) ----------------
// D[j][p] = sum_c W[j][c] * X[c][p]. CTA: 128 j x 128 p. Warp: 32 j x 64 p.
// K-chunk 32. SMEM rows padded to 20 u32 (80B) -> bank-conflict-free direct
// fragment loads (no ldmatrix, no swizzle). Double-buffered staging.
// Per-buffer u32 layout: Ah@0(2560) Al@2560 Bh@5120 Bl@7680; buffer=10240 u32.
#define SMEM_TOT 81920   // 2*40960 staging; epilogue buf 128*132*4=67584 fits

template <int CFG>
__global__ __launch_bounds__(256)
void gemm_tc(const float* __restrict__ Xext, const float* __restrict__ Bias,
             float* __restrict__ Cext)
{
    constexpr int K    = (CFG == 0 || CFG == 4) ? 512 : 256;
    constexpr int NCH  = K / 32;
    constexpr int WOFS = (CFG == 0) ? OWQ : (CFG == 1) ? OWK : (CFG == 2) ? OWV
                       : (CFG == 3) ? OWO : (CFG == 4) ? OWE : OWC;
    extern __shared__ char smem[];
    uint32_t* S32 = (uint32_t*)smem;
    const int tid = threadIdx.x, wid = tid >> 5, lane = tid & 31;
    const int lq = lane & 3, lr = lane >> 2;
    const int m0w = (wid >> 1) * 32;    // warp j offset
    const int n0w = (wid & 1) * 64;     // warp p offset
    const int b  = blockIdx.z;
    const int P0 = blockIdx.x * 128;
    const int J0 = blockIdx.y * 128;

    const float* X = (CFG == 3) ? g_cin : (CFG == 5) ? g_efp : Xext;
    const float* Xb = X + (size_t)b * K * HW;

    // B staging: thread covers c-pair (tid&15), 8 pixels (tid>>4)
    const int cpair = tid & 15, pg = tid >> 4;
    const float* xs0 = Xb + (size_t)(2 * cpair) * HW + P0 + pg * 8;
    const float* gs0 = (CFG == 5)
        ? (g_comb + (size_t)b * 256 * HW + (size_t)(2 * cpair) * HW + P0 + pg * 8) : nullptr;
    // A staging: thread covers weight row (tid>>1), half (tid&1)
    const int jrow = tid >> 1, half = tid & 1;
    const uint4* wh4 = (const uint4*)(g_wh + WOFS + (size_t)(J0 + jrow) * (K >> 1)) + half * 2;
    const uint4* wl4 = (const uint4*)(g_wl + WOFS + (size_t)(J0 + jrow) * (K >> 1)) + half * 2;

    float acc[2][8][4];
#pragma unroll
    for (int i = 0; i < 2; i++)
#pragma unroll
        for (int j = 0; j < 8; j++)
#pragma unroll
            for (int k = 0; k < 4; k++) acc[i][j][k] = 0.f;

    float4 xb4[4];          // [0,1]=even-c 8p, [2,3]=odd-c 8p
    uint4 whr[2], wlr[2];

#define LOADCH(ch) { \
    const float* s0 = xs0 + (size_t)(ch) * 32 * HW; \
    xb4[0] = *(const float4*)(s0);           xb4[1] = *(const float4*)(s0 + 4); \
    xb4[2] = *(const float4*)(s0 + HW);      xb4[3] = *(const float4*)(s0 + HW + 4); \
    if (CFG == 5) { \
        const float* g0 = gs0 + (size_t)(ch) * 32 * HW; \
        float4 a0 = *(const float4*)(g0),      a1 = *(const float4*)(g0 + 4); \
        float4 a2 = *(const float4*)(g0 + HW), a3 = *(const float4*)(g0 + HW + 4); \
        xb4[0].x *= a0.x; xb4[0].y *= a0.y; xb4[0].z *= a0.z; xb4[0].w *= a0.w; \
        xb4[1].x *= a1.x; xb4[1].y *= a1.y; xb4[1].z *= a1.z; xb4[1].w *= a1.w; \
        xb4[2].x *= a2.x; xb4[2].y *= a2.y; xb4[2].z *= a2.z; xb4[2].w *= a2.w; \
        xb4[3].x *= a3.x; xb4[3].y *= a3.y; xb4[3].z *= a3.z; xb4[3].w *= a3.w; \
    } \
    whr[0] = wh4[(ch) * 4]; whr[1] = wh4[(ch) * 4 + 1]; \
    wlr[0] = wl4[(ch) * 4]; wlr[1] = wl4[(ch) * 4 + 1]; }

#define STORECH(nb) { \
    uint32_t* B0 = S32 + (nb) * 10240; \
    uint32_t* Ah = B0;            uint32_t* Al = B0 + 2560; \
    uint32_t* Bh = B0 + 5120;     uint32_t* Bl = B0 + 7680; \
    *(uint4*)(Ah + jrow * 20 + half * 8)     = whr[0]; \
    *(uint4*)(Ah + jrow * 20 + half * 8 + 4) = whr[1]; \
    *(uint4*)(Al + jrow * 20 + half * 8)     = wlr[0]; \
    *(uint4*)(Al + jrow * 20 + half * 8 + 4) = wlr[1]; \
    const float* pe = (const float*)&xb4[0]; \
    const float* po = (const float*)&xb4[2]; \
_Pragma("unroll") \
    for (int i = 0; i < 8; i++) { \
        float r0, r1; \
        Bh[(pg * 8 + i) * 20 + cpair] = pack_hi(pe[i], po[i], r0, r1); \
        Bl[(pg * 8 + i) * 20 + cpair] = pack2(r0, r1); \
    } }

    LOADCH(0);
    STORECH(0);
    __syncthreads();

    for (int ch = 0; ch < NCH; ch++) {
        if (ch + 1 < NCH) LOADCH(ch + 1);
        uint32_t* B0 = S32 + (ch & 1) * 10240;
        uint32_t* Ah = B0;          uint32_t* Al = B0 + 2560;
        uint32_t* Bh = B0 + 5120;   uint32_t* Bl = B0 + 7680;
#pragma unroll
        for (int ks = 0; ks < 2; ks++) {
            uint32_t ah[2][4], al[2][4];
#pragma unroll
            for (int mt = 0; mt < 2; mt++) {
                int o = (m0w + mt * 16 + lr) * 20 + ks * 8 + lq;
                ah[mt][0] = Ah[o];       ah[mt][1] = Ah[o + 160];
                ah[mt][2] = Ah[o + 4];   ah[mt][3] = Ah[o + 164];
                al[mt][0] = Al[o];       al[mt][1] = Al[o + 160];
                al[mt][2] = Al[o + 4];   al[mt][3] = Al[o + 164];
            }
#pragma unroll
            for (int g = 0; g < 4; g++) {
#pragma unroll
                for (int sub = 0; sub < 2; sub++) {
                    int o = (n0w + g * 16 + sub * 8 + lr) * 20 + ks * 8 + lq;
                    uint32_t bh2[2] = { Bh[o], Bh[o + 4] };
                    uint32_t bl2[2] = { Bl[o], Bl[o + 4] };
#pragma unroll
                    for (int mt = 0; mt < 2; mt++) {
                        float* a = acc[mt][g * 2 + sub];
                        mma16(a, ah[mt], bh2);
                        mma16(a, al[mt], bh2);
                        mma16(a, ah[mt], bl2);
                    }
                }
            }
        }
        if (ch + 1 < NCH) STORECH((ch + 1) & 1);
        __syncthreads();
    }
#undef LOADCH
#undef STORECH

    // ---- epilogue: stage acc [j][p] in smem, then coalesced stores ----
    float* buf = (float*)smem;   // stride 132 floats per j-row
#pragma unroll
    for (int mt = 0; mt < 2; mt++) {
#pragma unroll
        for (int nt = 0; nt < 8; nt++) {
            int ml = m0w + mt * 16 + lr;
            int nl = n0w + nt * 8 + lq * 2;
            const float* ac = acc[mt][nt];
            buf[ml * 132 + nl]           = ac[0];
            buf[ml * 132 + nl + 1]       = ac[1];
            buf[(ml + 8) * 132 + nl]     = ac[2];
            buf[(ml + 8) * 132 + nl + 1] = ac[3];
        }
    }
    __syncthreads();

    const int pcol = lane * 4;
    float4 rp = {0, 0, 0, 0}, apv = {0, 0, 0, 0};
    if (CFG <= 2) {
        const float* rv = (CFG == 0) ? g_rf : g_rg;
        const float* av = (CFG == 0) ? g_af : g_ag;
        rp  = *(const float4*)(rv + (size_t)b * HW + P0 + pcol);
        apv = *(const float4*)(av + (size_t)b * HW + P0 + pcol);
    }
    float* Cb = ((CFG == 0) ? g_q : (CFG == 1) ? g_k : (CFG == 2) ? g_v
               : (CFG == 3) ? g_comb : (CFG == 4) ? g_efp : Cext)
              + (size_t)b * 256 * HW;
#pragma unroll
    for (int it = 0; it < 16; it++) {
        int jl = it * 8 + wid;
        int j = J0 + jl;
        float4 v = *(const float4*)(buf + jl * 132 + pcol);
        float4 o;
        if (CFG <= 2) {
            const float* Sv = (CFG == 0) ? g_Sq : (CFG == 1) ? g_Sk : g_Sv;
            const float* Tv = (CFG == 0) ? g_Tq : (CFG == 1) ? g_Tk : g_Tv;
            float S = Sv[j], T = Tv[j];
            o.x = fmaf(rp.x, v.x, fmaf(apv.x, S, T));
            o.y = fmaf(rp.y, v.y, fmaf(apv.y, S, T));
            o.z = fmaf(rp.z, v.z, fmaf(apv.z, S, T));
            o.w = fmaf(rp.w, v.w, fmaf(apv.w, S, T));
        } else if (CFG <= 4) {
            float bb = Bias[j];
            o.x = v.x + bb; o.y = v.y + bb; o.z = v.z + bb; o.w = v.w + bb;
        } else {
            float fs = g_fs[j], fb = g_fb[j];
            o.x = fmaxf(fmaf(v.x, fs, fb), 0.f);
            o.y = fmaxf(fmaf(v.y, fs, fb), 0.f);
            o.z = fmaxf(fmaf(v.z, fs, fb), 0.f);
            o.w = fmaxf(fmaf(v.w, fs, fb), 0.f);
        }
        *(float4*)(Cb + (size_t)j * HW + P0 + pcol) = o;
    }
}

// ---------------- pool (proven R5 version, channel-major) ----------------
__global__ void pool_kernel()
{
    int bc = blockIdx.x;         // b*4 + cell_row
    int b  = bc >> 2;
    int ch = bc & 3;
    int d0 = threadIdx.x >> 2;
    int cw = threadIdx.x & 3;

    for (int dc = 0; dc < 4; dc++) {
        int d = dc * 64 + d0;
        size_t base = (size_t)(b * 256 + d) * HW + (size_t)(ch * 16) * 64 + cw * 16;
        float mx = -3.4e38f, sm = 0.f;
        for (int hh = 0; hh < 16; hh++) {
            const float4* kr = (const float4*)(g_k + base + hh * 64);
            const float4* vr = (const float4*)(g_v + base + hh * 64);
#pragma unroll
            for (int i = 0; i < 4; i++) {
                float4 kv = kr[i], vv = vr[i];
                mx = fmaxf(mx, fmaxf(fmaxf(kv.x, kv.y), fmaxf(kv.z, kv.w)));
                sm += (vv.x + vv.y) + (vv.z + vv.w);
            }
        }
        int cell = ch * 4 + cw;
        g_kp[(b * 16 + cell) * 256 + d] = mx;
        g_vp[(b * 16 + cell) * 256 + d] = sm * (1.0f / 256.0f);
    }
}

// ---------------- pooled attention (proven R5 version) ----------------
__global__ __launch_bounds__(256)
void attn_kernel()
{
    __shared__ float ks[4096];
    __shared__ float vs[4096];
    int b   = blockIdx.y;
    int pix = blockIdx.x * 256 + threadIdx.x;

    for (int i = threadIdx.x; i < 4096; i += 256) {
        ks[i] = g_kp[b * 4096 + i];
        vs[i] = g_vp[b * 4096 + i];
    }
    __syncthreads();

    float s[16];
#pragma unroll
    for (int t = 0; t < 16; t++) s[t] = 0.f;

    const float* qb = g_q + (size_t)b * 256 * HW + pix;
    for (int d = 0; d < 256; d++) {
        float qd = qb[(size_t)d * HW];
#pragma unroll
        for (int t = 0; t < 16; t++)
            s[t] = fmaf(qd, ks[t * 256 + d], s[t]);
    }
    float m = -3.4e38f;
#pragma unroll
    for (int t = 0; t < 16; t++) { s[t] *= 0.0625f; m = fmaxf(m, s[t]); }
    float sum = 0.f;
#pragma unroll
    for (int t = 0; t < 16; t++) { s[t] = __expf(s[t] - m); sum += s[t]; }
    float inv = 1.0f / sum;
#pragma unroll
    for (int t = 0; t < 16; t++) s[t] *= inv;

    float* ab = g_a + (size_t)b * 256 * HW + pix;
    for (int d = 0; d < 256; d++) {
        float acc = 0.f;
#pragma unroll
        for (int t = 0; t < 16; t++)
            acc = fmaf(s[t], vs[t * 256 + d], acc);
        ab[(size_t)d * HW] = acc;
    }
}

// ---------------- depthwise 3x3 + attn add (proven R6 version) ----------------
__global__ __launch_bounds__(256)
void dwadd_kernel(const float* __restrict__ dwk)
{
    int bc   = blockIdx.y;             // b*256 + c
    int c    = bc & 255;
    int pix0 = (blockIdx.x * 256 + threadIdx.x) * 4;
    int h = pix0 >> 6, w0 = pix0 & 63;

    float k0 = dwk[c * 9 + 0], k1 = dwk[c * 9 + 1], k2 = dwk[c * 9 + 2];
    float k3 = dwk[c * 9 + 3], k4 = dwk[c * 9 + 4], k5 = dwk[c * 9 + 5];
    float k6 = dwk[c * 9 + 6], k7 = dwk[c * 9 + 7], k8 = dwk[c * 9 + 8];

    const float* qc = g_q + (size_t)bc * HW;
    const float* ac = g_a + (size_t)bc * HW;
    float*       oc = g_cin + (size_t)bc * HW;

    float acc[4];
#pragma unroll
    for (int i = 0; i < 4; i++) acc[i] = ac[pix0 + i];

#pragma unroll
    for (int dy = -1; dy <= 1; dy++) {
        int hh = h + dy;
        if (hh < 0 || hh > 63) continue;
        const float* row = qc + hh * 64;
        float ka = (dy == -1) ? k0 : (dy == 0) ? k3 : k6;
        float kb = (dy == -1) ? k1 : (dy == 0) ? k4 : k7;
        float kc = (dy == -1) ? k2 : (dy == 0) ? k5 : k8;
        float x[6];
#pragma unroll
        for (int i = 0; i < 6; i++) {
            int ww = w0 - 1 + i;
            x[i] = (ww >= 0 && ww <= 63) ? row[ww] : 0.0f;
        }
#pragma unroll
        for (int i = 0; i < 4; i++) {
            acc[i] = fmaf(ka, x[i], acc[i]);
            acc[i] = fmaf(kb, x[i + 1], acc[i]);
            acc[i] = fmaf(kc, x[i + 2], acc[i]);
        }
    }
#pragma unroll
    for (int i = 0; i < 4; i++) oc[pix0 + i] = acc[i];
}

// ---------------- launch ----------------
extern "C" void kernel_launch(void* const* d_in, const int* in_sizes, int n_in,
                              void* d_out, int out_size)
{
    const float* e_f    = (const float*)d_in[0];
    const float* e_g    = (const float*)d_in[1];
    const float* ln_f_g = (const float*)d_in[4];
    const float* ln_f_b = (const float*)d_in[5];
    const float* ln_g_g = (const float*)d_in[6];
    const float* ln_g_b = (const float*)d_in[7];
    const float* wq     = (const float*)d_in[8];
    const float* bq     = (const float*)d_in[9];
    const float* wk     = (const float*)d_in[10];
    const float* bk     = (const float*)d_in[11];
    const float* wv     = (const float*)d_in[12];
    const float* bv     = (const float*)d_in[13];
    const float* wo     = (const float*)d_in[14];
    const float* bo     = (const float*)d_in[15];
    const float* dwk    = (const float*)d_in[16];
    const float* efp_w  = (const float*)d_in[17];
    const float* efp_b  = (const float*)d_in[18];
    const float* outc_w = (const float*)d_in[19];
    const float* outc_b = (const float*)d_in[20];
    const float* bn_g   = (const float*)d_in[21];
    const float* bn_b   = (const float*)d_in[22];
    const float* bn_m   = (const float*)d_in[23];
    const float* bn_v   = (const float*)d_in[24];
    float* out = (float*)d_out;

    cudaFuncSetAttribute((const void*)gemm_tc<0>, cudaFuncAttributeMaxDynamicSharedMemorySize, SMEM_TOT);
    cudaFuncSetAttribute((const void*)gemm_tc<1>, cudaFuncAttributeMaxDynamicSharedMemorySize, SMEM_TOT);
    cudaFuncSetAttribute((const void*)gemm_tc<2>, cudaFuncAttributeMaxDynamicSharedMemorySize, SMEM_TOT);
    cudaFuncSetAttribute((const void*)gemm_tc<3>, cudaFuncAttributeMaxDynamicSharedMemorySize, SMEM_TOT);
    cudaFuncSetAttribute((const void*)gemm_tc<4>, cudaFuncAttributeMaxDynamicSharedMemorySize, SMEM_TOT);
    cudaFuncSetAttribute((const void*)gemm_tc<5>, cudaFuncAttributeMaxDynamicSharedMemorySize, SMEM_TOT);

    fold_kernel<<<1024, 256>>>(wq, ln_f_g, wk, wv, ln_g_g, wo, efp_w, outc_w);
    vec_kernel<<<4, 256>>>(wq, bq, ln_f_g, ln_f_b, wk, bk, wv, bv, ln_g_g, ln_g_b,
                           outc_b, bn_g, bn_b, bn_m, bn_v);
    stats_kernel<0><<<128, 256>>>(e_f);
    stats_kernel<1><<<128, 256>>>(e_g);

    dim3 gg(32, 2, 8);
    gemm_tc<0><<<gg, 256, SMEM_TOT>>>(e_f, nullptr, nullptr);   // Q
    gemm_tc<1><<<gg, 256, SMEM_TOT>>>(e_g, nullptr, nullptr);   // K
    gemm_tc<2><<<gg, 256, SMEM_TOT>>>(e_g, nullptr, nullptr);   // V

    pool_kernel<<<32, 256>>>();
    attn_kernel<<<dim3(16, 8), 256>>>();
    dwadd_kernel<<<dim3(4, 2048), 256>>>(dwk);

    gemm_tc<3><<<gg, 256, SMEM_TOT>>>(nullptr, bo, nullptr);    // comb = wo(cin)+bo
    gemm_tc<4><<<gg, 256, SMEM_TOT>>>(e_f, efp_b, nullptr);     // efp
    gemm_tc<5><<<gg, 256, SMEM_TOT>>>(nullptr, nullptr, out);   // gated + BN + ReLU
}

// round 16
// speedup vs baseline: 1.8775x; 1.7230x over previous
#include <cuda_runtime.h>
#include <cuda_fp16.h>
#include <cstdint>

#define HW 4096
#define NB 8

// ---------------- device scratch (channel-major [b][c][p]) ----------------
__device__ uint32_t g_wh[262144];   // packed fp16 hi weights, [j][c/2], K-major
__device__ uint32_t g_wl[262144];   // packed fp16 lo (residual)
#define OWQ 0
#define OWK 65536
#define OWV 98304
#define OWO 131072
#define OWE 163840
#define OWC 229376
__device__ float g_Sq[256], g_Tq[256];
__device__ float g_Sk[256], g_Tk[256];
__device__ float g_Sv[256], g_Tv[256];
__device__ float g_fs[256], g_fb[256];
__device__ float g_rf[NB * HW], g_af[NB * HW];
__device__ float g_rg[NB * HW], g_ag[NB * HW];
__device__ float g_q   [NB * 256 * HW];
__device__ float g_k   [NB * 256 * HW];
__device__ float g_v   [NB * 256 * HW];
__device__ float g_a   [NB * 256 * HW];
__device__ float g_cin [NB * 256 * HW];
__device__ float g_comb[NB * 256 * HW];
__device__ float g_efp [NB * 256 * HW];
__device__ float g_kp[NB * 16 * 256];
__device__ float g_vp[NB * 16 * 256];

// ---------------- helpers ----------------
__device__ __forceinline__ uint32_t pack_hi(float x0, float x1, float& r0, float& r1) {
    __half h0 = __float2half_rn(x0), h1 = __float2half_rn(x1);
    r0 = x0 - __half2float(h0);
    r1 = x1 - __half2float(h1);
    return (uint32_t)__half_as_ushort(h0) | ((uint32_t)__half_as_ushort(h1) << 16);
}
__device__ __forceinline__ uint32_t pack2(float x0, float x1) {
    __half h0 = __float2half_rn(x0), h1 = __float2half_rn(x1);
    return (uint32_t)__half_as_ushort(h0) | ((uint32_t)__half_as_ushort(h1) << 16);
}
__device__ __forceinline__ void mma16(float* c, const uint32_t* a, const uint32_t* b) {
    asm volatile(
        "mma.sync.aligned.m16n8k16.row.col.f32.f16.f16.f32 "
        "{%0,%1,%2,%3}, {%4,%5,%6,%7}, {%8,%9}, {%0,%1,%2,%3};"
        : "+f"(c[0]), "+f"(c[1]), "+f"(c[2]), "+f"(c[3])
        : "r"(a[0]), "r"(a[1]), "r"(a[2]), "r"(a[3]), "r"(b[0]), "r"(b[1]));
}

// ---------------- prep: split+pack all weights (hi/lo fp16) ----------------
__global__ void fold_kernel(const float* __restrict__ wq, const float* __restrict__ gf,
                            const float* __restrict__ wk, const float* __restrict__ wv,
                            const float* __restrict__ gg, const float* __restrict__ wo,
                            const float* __restrict__ efp_w, const float* __restrict__ outc_w)
{
    int idx = blockIdx.x * 256 + threadIdx.x;   // 0..262143
    float x0, x1;
    if (idx < 65536) {                                    // wq folded, transpose -> [j][c]
        int j = idx >> 8, c = (idx & 255) * 2;
        x0 = wq[c * 256 + j] * gf[c];
        x1 = wq[(c + 1) * 256 + j] * gf[c + 1];
    } else if (idx < 98304) {                             // wk folded
        int r = idx - 65536, j = r >> 7, c = (r & 127) * 2;
        x0 = wk[c * 256 + j] * gg[c];
        x1 = wk[(c + 1) * 256 + j] * gg[c + 1];
    } else if (idx < 131072) {                            // wv folded
        int r = idx - 98304, j = r >> 7, c = (r & 127) * 2;
        x0 = wv[c * 256 + j] * gg[c];
        x1 = wv[(c + 1) * 256 + j] * gg[c + 1];
    } else if (idx < 163840) {                            // wo transpose
        int r = idx - 131072, j = r >> 7, c = (r & 127) * 2;
        x0 = wo[c * 256 + j];
        x1 = wo[(c + 1) * 256 + j];
    } else if (idx < 229376) {                            // efp_w direct [j][c]
        int r = idx - 163840, j = r >> 8, c = (r & 255) * 2;
        x0 = efp_w[j * 512 + c];
        x1 = efp_w[j * 512 + c + 1];
    } else {                                              // outc_w direct
        int r = idx - 229376, j = r >> 7, c = (r & 127) * 2;
        x0 = outc_w[j * 256 + c];
        x1 = outc_w[j * 256 + c + 1];
    }
    float r0, r1;
    g_wh[idx] = pack_hi(x0, x1, r0, r1);
    g_wl[idx] = pack2(r0, r1);
}

__global__ void vec_kernel(const float* __restrict__ wq, const float* __restrict__ bq,
                           const float* __restrict__ gf, const float* __restrict__ bf,
                           const float* __restrict__ wk, const float* __restrict__ bk,
                           const float* __restrict__ wv, const float* __restrict__ bv,
                           const float* __restrict__ gg, const float* __restrict__ bg,
                           const float* __restrict__ outc_b,
                           const float* __restrict__ bn_g, const float* __restrict__ bn_b,
                           const float* __restrict__ bn_m, const float* __restrict__ bn_v)
{
    int j = threadIdx.x;
    if (blockIdx.x == 0) {
        float S = 0.f, T = 0.f;
        for (int c = 0; c < 512; c++) {
            float w = wq[c * 256 + j];
            S = fmaf(w, gf[c], S); T = fmaf(w, bf[c], T);
        }
        g_Sq[j] = S; g_Tq[j] = T + bq[j];
    } else if (blockIdx.x == 1) {
        float S = 0.f, T = 0.f;
        for (int c = 0; c < 256; c++) {
            float w = wk[c * 256 + j];
            S = fmaf(w, gg[c], S); T = fmaf(w, bg[c], T);
        }
        g_Sk[j] = S; g_Tk[j] = T + bk[j];
    } else if (blockIdx.x == 2) {
        float S = 0.f, T = 0.f;
        for (int c = 0; c < 256; c++) {
            float w = wv[c * 256 + j];
            S = fmaf(w, gg[c], S); T = fmaf(w, bg[c], T);
        }
        g_Sv[j] = S; g_Tv[j] = T + bv[j];
    } else {
        float sc = bn_g[j] * rsqrtf(bn_v[j] + 1e-5f);
        g_fs[j] = sc;
        g_fb[j] = (outc_b[j] - bn_m[j]) * sc + bn_b[j];
    }
}

// ---------------- per-pixel LN stats (128-thread blocks, 256 blocks) -------
template <int WHICH>
__global__ __launch_bounds__(128)
void stats_kernel(const float* __restrict__ X)
{
    constexpr int C = (WHICH == 0) ? 512 : 256;
    int gid = blockIdx.x * 128 + threadIdx.x;
    const float* base = X + (size_t)(gid >> 12) * C * HW + (gid & (HW - 1));
    float s = 0.f, s2 = 0.f;
#pragma unroll 8
    for (int c = 0; c < C; c++) {
        float v = base[(size_t)c * HW];
        s += v; s2 = fmaf(v, v, s2);
    }
    const float invC = 1.0f / (float)C;
    float m = s * invC;
    float var = fmaf(-m, m, s2 * invC);
    float r = rsqrtf(var + 1e-5f);
    if (WHICH == 0) { g_rf[gid] = r; g_af[gid] = -r * m; }
    else            { g_rg[gid] = r; g_ag[gid] = -r * m; }
}

// ---------------- mma.sync fp16 2-term GEMM (channel-major) ----------------
// D[j][p] = sum_c W[j][c] * X[c][p] with W = Wh + Wl (pre-split fp16 pair),
// X rounded once to fp16:  D ~= Wh*Xh + Wl*Xh.
// CTA: 128 j x 128 p, warp 32 j x 64 p, K-chunk 32. SMEM rows padded to 20
// u32 -> conflict-free direct fragment loads. Double-buffered staging.
// Per-buffer u32: Ah@0(2560) Al@2560 Bh@5120; buffer = 7680 u32 (30KB).
#define SMEM_TOT 67584   // epilogue buf 128*132*4 dominates

template <int CFG>
__global__ __launch_bounds__(256)
void gemm_tc(const float* __restrict__ Xext, const float* __restrict__ Bias,
             float* __restrict__ Cext)
{
    constexpr int K    = (CFG == 0 || CFG == 4) ? 512 : 256;
    constexpr int NCH  = K / 32;
    constexpr int WOFS = (CFG == 0) ? OWQ : (CFG == 1) ? OWK : (CFG == 2) ? OWV
                       : (CFG == 3) ? OWO : (CFG == 4) ? OWE : OWC;
    extern __shared__ char smem[];
    uint32_t* S32 = (uint32_t*)smem;
    const int tid = threadIdx.x, wid = tid >> 5, lane = tid & 31;
    const int lq = lane & 3, lr = lane >> 2;
    const int m0w = (wid >> 1) * 32;    // warp j offset
    const int n0w = (wid & 1) * 64;     // warp p offset
    const int b  = blockIdx.z;
    const int P0 = blockIdx.x * 128;
    const int J0 = blockIdx.y * 128;

    const float* X = (CFG == 3) ? g_cin : (CFG == 5) ? g_efp : Xext;
    const float* Xb = X + (size_t)b * K * HW;

    // B staging: thread covers c-pair (tid&15), 8 pixels (tid>>4)
    const int cpair = tid & 15, pg = tid >> 4;
    const float* xs0 = Xb + (size_t)(2 * cpair) * HW + P0 + pg * 8;
    const float* gs0 = (CFG == 5)
        ? (g_comb + (size_t)b * 256 * HW + (size_t)(2 * cpair) * HW + P0 + pg * 8) : nullptr;
    // A staging: thread covers weight row (tid>>1), half (tid&1)
    const int jrow = tid >> 1, half = tid & 1;
    const uint4* wh4 = (const uint4*)(g_wh + WOFS + (size_t)(J0 + jrow) * (K >> 1)) + half * 2;
    const uint4* wl4 = (const uint4*)(g_wl + WOFS + (size_t)(J0 + jrow) * (K >> 1)) + half * 2;

    float acc[2][8][4];
#pragma unroll
    for (int i = 0; i < 2; i++)
#pragma unroll
        for (int j = 0; j < 8; j++)
#pragma unroll
            for (int k = 0; k < 4; k++) acc[i][j][k] = 0.f;

    float4 xb4[4];          // [0,1]=even-c 8p, [2,3]=odd-c 8p
    uint4 whr[2], wlr[2];

#define LOADCH(ch) { \
    const float* s0 = xs0 + (size_t)(ch) * 32 * HW; \
    xb4[0] = *(const float4*)(s0);           xb4[1] = *(const float4*)(s0 + 4); \
    xb4[2] = *(const float4*)(s0 + HW);      xb4[3] = *(const float4*)(s0 + HW + 4); \
    if (CFG == 5) { \
        const float* g0 = gs0 + (size_t)(ch) * 32 * HW; \
        float4 a0 = *(const float4*)(g0),      a1 = *(const float4*)(g0 + 4); \
        float4 a2 = *(const float4*)(g0 + HW), a3 = *(const float4*)(g0 + HW + 4); \
        xb4[0].x *= a0.x; xb4[0].y *= a0.y; xb4[0].z *= a0.z; xb4[0].w *= a0.w; \
        xb4[1].x *= a1.x; xb4[1].y *= a1.y; xb4[1].z *= a1.z; xb4[1].w *= a1.w; \
        xb4[2].x *= a2.x; xb4[2].y *= a2.y; xb4[2].z *= a2.z; xb4[2].w *= a2.w; \
        xb4[3].x *= a3.x; xb4[3].y *= a3.y; xb4[3].z *= a3.z; xb4[3].w *= a3.w; \
    } \
    whr[0] = wh4[(ch) * 4]; whr[1] = wh4[(ch) * 4 + 1]; \
    wlr[0] = wl4[(ch) * 4]; wlr[1] = wl4[(ch) * 4 + 1]; }

#define STORECH(nb) { \
    uint32_t* B0 = S32 + (nb) * 7680; \
    uint32_t* Ah = B0;            uint32_t* Al = B0 + 2560; \
    uint32_t* Bh = B0 + 5120; \
    *(uint4*)(Ah + jrow * 20 + half * 8)     = whr[0]; \
    *(uint4*)(Ah + jrow * 20 + half * 8 + 4) = whr[1]; \
    *(uint4*)(Al + jrow * 20 + half * 8)     = wlr[0]; \
    *(uint4*)(Al + jrow * 20 + half * 8 + 4) = wlr[1]; \
    const float* pe = (const float*)&xb4[0]; \
    const float* po = (const float*)&xb4[2]; \
_Pragma("unroll") \
    for (int i = 0; i < 8; i++) { \
        Bh[(pg * 8 + i) * 20 + cpair] = pack2(pe[i], po[i]); \
    } }

    LOADCH(0);
    STORECH(0);
    __syncthreads();

    for (int ch = 0; ch < NCH; ch++) {
        if (ch + 1 < NCH) LOADCH(ch + 1);
        uint32_t* B0 = S32 + (ch & 1) * 7680;
        uint32_t* Ah = B0;          uint32_t* Al = B0 + 2560;
        uint32_t* Bh = B0 + 5120;
#pragma unroll
        for (int ks = 0; ks < 2; ks++) {
            uint32_t ah[2][4], al[2][4];
#pragma unroll
            for (int mt = 0; mt < 2; mt++) {
                int o = (m0w + mt * 16 + lr) * 20 + ks * 8 + lq;
                ah[mt][0] = Ah[o];       ah[mt][1] = Ah[o + 160];
                ah[mt][2] = Ah[o + 4];   ah[mt][3] = Ah[o + 164];
                al[mt][0] = Al[o];       al[mt][1] = Al[o + 160];
                al[mt][2] = Al[o + 4];   al[mt][3] = Al[o + 164];
            }
#pragma unroll
            for (int g = 0; g < 4; g++) {
#pragma unroll
                for (int sub = 0; sub < 2; sub++) {
                    int o = (n0w + g * 16 + sub * 8 + lr) * 20 + ks * 8 + lq;
                    uint32_t bh2[2] = { Bh[o], Bh[o + 4] };
#pragma unroll
                    for (int mt = 0; mt < 2; mt++) {
                        float* a = acc[mt][g * 2 + sub];
                        mma16(a, ah[mt], bh2);
                        mma16(a, al[mt], bh2);
                    }
                }
            }
        }
        if (ch + 1 < NCH) STORECH((ch + 1) & 1);
        __syncthreads();
    }
#undef LOADCH
#undef STORECH

    // ---- epilogue: stage acc [j][p] in smem, then coalesced stores ----
    float* buf = (float*)smem;   // stride 132 floats per j-row
#pragma unroll
    for (int mt = 0; mt < 2; mt++) {
#pragma unroll
        for (int nt = 0; nt < 8; nt++) {
            int ml = m0w + mt * 16 + lr;
            int nl = n0w + nt * 8 + lq * 2;
            const float* ac = acc[mt][nt];
            buf[ml * 132 + nl]           = ac[0];
            buf[ml * 132 + nl + 1]       = ac[1];
            buf[(ml + 8) * 132 + nl]     = ac[2];
            buf[(ml + 8) * 132 + nl + 1] = ac[3];
        }
    }
    __syncthreads();

    const int pcol = lane * 4;
    float4 rp = {0, 0, 0, 0}, apv = {0, 0, 0, 0};
    if (CFG <= 2) {
        const float* rv = (CFG == 0) ? g_rf : g_rg;
        const float* av = (CFG == 0) ? g_af : g_ag;
        rp  = *(const float4*)(rv + (size_t)b * HW + P0 + pcol);
        apv = *(const float4*)(av + (size_t)b * HW + P0 + pcol);
    }
    float* Cb = ((CFG == 0) ? g_q : (CFG == 1) ? g_k : (CFG == 2) ? g_v
               : (CFG == 3) ? g_comb : (CFG == 4) ? g_efp : Cext)
              + (size_t)b * 256 * HW;
#pragma unroll
    for (int it = 0; it < 16; it++) {
        int jl = it * 8 + wid;
        int j = J0 + jl;
        float4 v = *(const float4*)(buf + jl * 132 + pcol);
        float4 o;
        if (CFG <= 2) {
            const float* Sv = (CFG == 0) ? g_Sq : (CFG == 1) ? g_Sk : g_Sv;
            const float* Tv = (CFG == 0) ? g_Tq : (CFG == 1) ? g_Tk : g_Tv;
            float S = Sv[j], T = Tv[j];
            o.x = fmaf(rp.x, v.x, fmaf(apv.x, S, T));
            o.y = fmaf(rp.y, v.y, fmaf(apv.y, S, T));
            o.z = fmaf(rp.z, v.z, fmaf(apv.z, S, T));
            o.w = fmaf(rp.w, v.w, fmaf(apv.w, S, T));
        } else if (CFG <= 4) {
            float bb = Bias[j];
            o.x = v.x + bb; o.y = v.y + bb; o.z = v.z + bb; o.w = v.w + bb;
        } else {
            float fs = g_fs[j], fb = g_fb[j];
            o.x = fmaxf(fmaf(v.x, fs, fb), 0.f);
            o.y = fmaxf(fmaf(v.y, fs, fb), 0.f);
            o.z = fmaxf(fmaf(v.z, fs, fb), 0.f);
            o.w = fmaxf(fmaf(v.w, fs, fb), 0.f);
        }
        *(float4*)(Cb + (size_t)j * HW + P0 + pcol) = o;
    }
}

// ---------------- pool: 128 blocks (b x cell_row x chan-quarter) ----------
__global__ __launch_bounds__(256)
void pool_kernel()
{
    int bx = blockIdx.x;         // b*16 + ch*4 + dc
    int b  = bx >> 4;
    int ch = (bx >> 2) & 3;      // cell row
    int dc = bx & 3;             // channel quarter
    int d0 = threadIdx.x >> 2;
    int cw = threadIdx.x & 3;

    int d = dc * 64 + d0;
    size_t base = (size_t)(b * 256 + d) * HW + (size_t)(ch * 16) * 64 + cw * 16;
    float mx = -3.4e38f, sm = 0.f;
    for (int hh = 0; hh < 16; hh++) {
        const float4* kr = (const float4*)(g_k + base + hh * 64);
        const float4* vr = (const float4*)(g_v + base + hh * 64);
#pragma unroll
        for (int i = 0; i < 4; i++) {
            float4 kv = kr[i], vv = vr[i];
            mx = fmaxf(mx, fmaxf(fmaxf(kv.x, kv.y), fmaxf(kv.z, kv.w)));
            sm += (vv.x + vv.y) + (vv.z + vv.w);
        }
    }
    int cell = ch * 4 + cw;
    g_kp[(b * 16 + cell) * 256 + d] = mx;
    g_vp[(b * 16 + cell) * 256 + d] = sm * (1.0f / 256.0f);
}

// ---------------- pooled attention (128-thread blocks, 256 blocks) --------
__global__ __launch_bounds__(128)
void attn_kernel()
{
    __shared__ float ks[4096];
    __shared__ float vs[4096];
    int b   = blockIdx.y;
    int pix = blockIdx.x * 128 + threadIdx.x;

    for (int i = threadIdx.x; i < 4096; i += 128) {
        ks[i] = g_kp[b * 4096 + i];
        vs[i] = g_vp[b * 4096 + i];
    }
    __syncthreads();

    float s[16];
#pragma unroll
    for (int t = 0; t < 16; t++) s[t] = 0.f;

    const float* qb = g_q + (size_t)b * 256 * HW + pix;
    for (int d = 0; d < 256; d++) {
        float qd = qb[(size_t)d * HW];
#pragma unroll
        for (int t = 0; t < 16; t++)
            s[t] = fmaf(qd, ks[t * 256 + d], s[t]);
    }
    float m = -3.4e38f;
#pragma unroll
    for (int t = 0; t < 16; t++) { s[t] *= 0.0625f; m = fmaxf(m, s[t]); }
    float sum = 0.f;
#pragma unroll
    for (int t = 0; t < 16; t++) { s[t] = __expf(s[t] - m); sum += s[t]; }
    float inv = 1.0f / sum;
#pragma unroll
    for (int t = 0; t < 16; t++) s[t] *= inv;

    float* ab = g_a + (size_t)b * 256 * HW + pix;
    for (int d = 0; d < 256; d++) {
        float acc = 0.f;
#pragma unroll
        for (int t = 0; t < 16; t++)
            acc = fmaf(s[t], vs[t * 256 + d], acc);
        ab[(size_t)d * HW] = acc;
    }
}

// ---------------- depthwise 3x3 + attn add (proven R6 version) ------------
__global__ __launch_bounds__(256)
void dwadd_kernel(const float* __restrict__ dwk)
{
    int bc   = blockIdx.y;             // b*256 + c
    int c    = bc & 255;
    int pix0 = (blockIdx.x * 256 + threadIdx.x) * 4;
    int h = pix0 >> 6, w0 = pix0 & 63;

    float k0 = dwk[c * 9 + 0], k1 = dwk[c * 9 + 1], k2 = dwk[c * 9 + 2];
    float k3 = dwk[c * 9 + 3], k4 = dwk[c * 9 + 4], k5 = dwk[c * 9 + 5];
    float k6 = dwk[c * 9 + 6], k7 = dwk[c * 9 + 7], k8 = dwk[c * 9 + 8];

    const float* qc = g_q + (size_t)bc * HW;
    const float* ac = g_a + (size_t)bc * HW;
    float*       oc = g_cin + (size_t)bc * HW;

    float acc[4];
#pragma unroll
    for (int i = 0; i < 4; i++) acc[i] = ac[pix0 + i];

#pragma unroll
    for (int dy = -1; dy <= 1; dy++) {
        int hh = h + dy;
        if (hh < 0 || hh > 63) continue;
        const float* row = qc + hh * 64;
        float ka = (dy == -1) ? k0 : (dy == 0) ? k3 : k6;
        float kb = (dy == -1) ? k1 : (dy == 0) ? k4 : k7;
        float kc = (dy == -1) ? k2 : (dy == 0) ? k5 : k8;
        float x[6];
#pragma unroll
        for (int i = 0; i < 6; i++) {
            int ww = w0 - 1 + i;
            x[i] = (ww >= 0 && ww <= 63) ? row[ww] : 0.0f;
        }
#pragma unroll
        for (int i = 0; i < 4; i++) {
            acc[i] = fmaf(ka, x[i], acc[i]);
            acc[i] = fmaf(kb, x[i + 1], acc[i]);
            acc[i] = fmaf(kc, x[i + 2], acc[i]);
        }
    }
#pragma unroll
    for (int i = 0; i < 4; i++) oc[pix0 + i] = acc[i];
}

// ---------------- launch ----------------
extern "C" void kernel_launch(void* const* d_in, const int* in_sizes, int n_in,
                              void* d_out, int out_size)
{
    const float* e_f    = (const float*)d_in[0];
    const float* e_g    = (const float*)d_in[1];
    const float* ln_f_g = (const float*)d_in[4];
    const float* ln_f_b = (const float*)d_in[5];
    const float* ln_g_g = (const float*)d_in[6];
    const float* ln_g_b = (const float*)d_in[7];
    const float* wq     = (const float*)d_in[8];
    const float* bq     = (const float*)d_in[9];
    const float* wk     = (const float*)d_in[10];
    const float* bk     = (const float*)d_in[11];
    const float* wv     = (const float*)d_in[12];
    const float* bv     = (const float*)d_in[13];
    const float* wo     = (const float*)d_in[14];
    const float* bo     = (const float*)d_in[15];
    const float* dwk    = (const float*)d_in[16];
    const float* efp_w  = (const float*)d_in[17];
    const float* efp_b  = (const float*)d_in[18];
    const float* outc_w = (const float*)d_in[19];
    const float* outc_b = (const float*)d_in[20];
    const float* bn_g   = (const float*)d_in[21];
    const float* bn_b   = (const float*)d_in[22];
    const float* bn_m   = (const float*)d_in[23];
    const float* bn_v   = (const float*)d_in[24];
    float* out = (float*)d_out;

    cudaFuncSetAttribute((const void*)gemm_tc<0>, cudaFuncAttributeMaxDynamicSharedMemorySize, SMEM_TOT);
    cudaFuncSetAttribute((const void*)gemm_tc<1>, cudaFuncAttributeMaxDynamicSharedMemorySize, SMEM_TOT);
    cudaFuncSetAttribute((const void*)gemm_tc<2>, cudaFuncAttributeMaxDynamicSharedMemorySize, SMEM_TOT);
    cudaFuncSetAttribute((const void*)gemm_tc<3>, cudaFuncAttributeMaxDynamicSharedMemorySize, SMEM_TOT);
    cudaFuncSetAttribute((const void*)gemm_tc<4>, cudaFuncAttributeMaxDynamicSharedMemorySize, SMEM_TOT);
    cudaFuncSetAttribute((const void*)gemm_tc<5>, cudaFuncAttributeMaxDynamicSharedMemorySize, SMEM_TOT);

    fold_kernel<<<1024, 256>>>(wq, ln_f_g, wk, wv, ln_g_g, wo, efp_w, outc_w);
    vec_kernel<<<4, 256>>>(wq, bq, ln_f_g, ln_f_b, wk, bk, wv, bv, ln_g_g, ln_g_b,
                           outc_b, bn_g, bn_b, bn_m, bn_v);
    stats_kernel<0><<<256, 128>>>(e_f);
    stats_kernel<1><<<256, 128>>>(e_g);

    dim3 gg(32, 2, 8);
    gemm_tc<0><<<gg, 256, SMEM_TOT>>>(e_f, nullptr, nullptr);   // Q
    gemm_tc<1><<<gg, 256, SMEM_TOT>>>(e_g, nullptr, nullptr);   // K
    gemm_tc<2><<<gg, 256, SMEM_TOT>>>(e_g, nullptr, nullptr);   // V

    pool_kernel<<<128, 256>>>();
    attn_kernel<<<dim3(32, 8), 128>>>();
    dwadd_kernel<<<dim3(4, 2048), 256>>>(dwk);

    gemm_tc<3><<<gg, 256, SMEM_TOT>>>(nullptr, bo, nullptr);    // comb = wo(cin)+bo
    gemm_tc<4><<<gg, 256, SMEM_TOT>>>(e_f, efp_b, nullptr);     // efp
    gemm_tc<5><<<gg, 256, SMEM_TOT>>>(nullptr, nullptr, out);   // gated + BN + ReLU
}